// round 11
// baseline (speedup 1.0000x reference)
#include <cuda_runtime.h>
#include <math.h>

// ToneStack: 3 cascaded low-shelf biquads over x:[64, 480000] fp32.
// Setup + ONE fused streaming kernel (decoupled lookback):
//   sweep1: warp-transpose staged SERIAL filter from zero state; writes the
//           zero-state output y0 into y (x read once) and per-chunk finals.
//   scan  : in-block tree (6x4 per warp, 5 warps) + lookback over <=24
//           same-row predecessors (volatile-load polling, no spin atomics).
//   sweep2: y[n] = y0[n] + V[n]. s_entry  (V[n] = c^T A^n, superposition);
//           y0 tiles re-read (L2-hot), 6 FMA/sample, coalesced store.

#define TLEN    480000
#define NROW    64
#define CHUNK   160              // 5 tiles of 32 samples
#define WCH     24               // chunks per warp
#define NWPB    5                // warps per block
#define BCH     (NWPB * WCH)     // 120 chunks per block
#define BROW    25               // blocks per row (120*160*25 = 480000)
#define GRID    (NROW * BROW)    // 1600
#define NLOOK   25
#define THREADS 160
#define C4      (CHUNK / 4)      // 40 float4 per chunk

__device__ float g_coef[15];         // per stage: b0, c1, c2, -a1, -a2
__device__ float g_T[36];            // A^CHUNK
__device__ float g_T4[36];           // T^4
__device__ float g_T24[36];          // T^24
__device__ float g_Tbp[NLOOK * 36];  // (T^120)^p, p = 0..24
__device__ float g_W6[6][CHUNK];     // state-reduction weights (transposed)
__device__ float g_V6[6][CHUNK];     // output-correction weights (transposed)
__device__ float g_F[GRID * 6];      // block aggregates
__device__ int   g_flag[GRID];       // publication flags

// ---------------------------------------------------------------- setup ----

__device__ void shelf_coefs(double fc, double gdb, double Q, double* out) {
    const double PI = 3.14159265358979323846;
    double A  = pow(10.0, gdb / 40.0);
    double w0 = 2.0 * PI * fc / 48000.0;
    double al = sin(w0) / (2.0 * Q);
    double cw = cos(w0);
    double sq = sqrt(A);
    double b0 = A * ((A + 1.0) - (A - 1.0) * cw + 2.0 * sq * al);
    double b1 = 2.0 * A * ((A - 1.0) - (A + 1.0) * cw);
    double b2 = A * ((A + 1.0) - (A - 1.0) * cw - 2.0 * sq * al);
    double a0 = (A + 1.0) + (A - 1.0) * cw + 2.0 * sq * al;
    double a1 = -2.0 * ((A - 1.0) + (A + 1.0) * cw);
    double a2 = (A + 1.0) + (A - 1.0) * cw - 2.0 * sq * al;
    b0 /= a0; b1 /= a0; b2 /= a0; a1 /= a0; a2 /= a0;
    out[0] = b0;
    out[1] = b1 - a1 * b0;   // c1
    out[2] = b2 - a2 * b0;   // c2
    out[3] = -a1;
    out[4] = -a2;
}

#define MATMUL(D, A_, B_)                                                     \
    do {                                                                      \
        if (tid < 36) {                                                       \
            int r_ = tid / 6, c_ = tid % 6;                                   \
            float acc_ = 0.f;                                                 \
            for (int k_ = 0; k_ < 6; k_++)                                    \
                acc_ += (A_)[r_ * 6 + k_] * (B_)[k_ * 6 + c_];                \
            (D)[tid] = acc_;                                                  \
        }                                                                     \
        __syncthreads();                                                      \
    } while (0)

__global__ void setup_kernel(const float* lg, const float* mg, const float* mfc,
                             const float* mq, const float* hg) {
    __shared__ double scoef[15];
    __shared__ double db[6];
    __shared__ float sP[8][36];   // A^(2^k), k = 0..7
    __shared__ float sQ[6][36];   // T^2, T^4, T^8, T^16, T^32, T^64
    __shared__ float sTb[36];
    __shared__ float M0[36], M1[36], M2[36];
    int tid = threadIdx.x;

    for (int i = tid; i < GRID; i += 256) g_flag[i] = 0;

    if (tid == 0) {
        double c[5];
        shelf_coefs(120.0, (double)*lg, (double)0.707f, c);
        for (int i = 0; i < 5; i++) { scoef[i] = c[i];      g_coef[i]      = (float)c[i]; }
        shelf_coefs((double)*mfc, (double)*mg, (double)*mq, c);
        for (int i = 0; i < 5; i++) { scoef[5 + i] = c[i];  g_coef[5 + i]  = (float)c[i]; }
        shelf_coefs(4000.0, (double)*hg, (double)0.707f, c);
        for (int i = 0; i < 5; i++) { scoef[10 + i] = c[i]; g_coef[10 + i] = (float)c[i]; }
    }
    __syncthreads();

    // one-step 6x6 matrix A (column j = step(e_j, x=0)); input vector b
    if (tid < 6) {
        double z[6] = {0, 0, 0, 0, 0, 0};
        z[tid] = 1.0;
        double u = 0.0;
        double ns[6];
        for (int st = 0; st < 3; st++) {
            double b0  = scoef[st * 5 + 0], c1 = scoef[st * 5 + 1], c2 = scoef[st * 5 + 2];
            double na1 = scoef[st * 5 + 3], na2 = scoef[st * 5 + 4];
            double z1 = z[2 * st], z2 = z[2 * st + 1];
            double y = b0 * u + z1;
            ns[2 * st]     = c1 * u + na1 * z1 + z2;
            ns[2 * st + 1] = c2 * u + na2 * z1;
            u = y;
        }
        for (int i = 0; i < 6; i++) M0[i * 6 + tid] = (float)ns[i];
    }
    if (tid == 0) {
        double y0 = scoef[0];
        double y1 = scoef[5] * y0;
        db[0] = scoef[1];  db[1] = scoef[2];
        db[2] = scoef[6] * y0;   db[3] = scoef[7] * y0;
        db[4] = scoef[11] * y1;  db[5] = scoef[12] * y1;
    }
    __syncthreads();

    // A^(2^k), k=0..7
    if (tid < 36) sP[0][tid] = M0[tid];
    __syncthreads();
    MATMUL(M1, M0, M0);  if (tid < 36) sP[1][tid] = M1[tid];   // A^2
    MATMUL(M0, M1, M1);  if (tid < 36) sP[2][tid] = M0[tid];   // A^4
    MATMUL(M1, M0, M0);  if (tid < 36) sP[3][tid] = M1[tid];   // A^8
    MATMUL(M0, M1, M1);  if (tid < 36) sP[4][tid] = M0[tid];   // A^16
    MATMUL(M1, M0, M0);  if (tid < 36) sP[5][tid] = M1[tid];   // A^32
    MATMUL(M0, M1, M1);  if (tid < 36) sP[6][tid] = M0[tid];   // A^64
    MATMUL(M1, M0, M0);  if (tid < 36) sP[7][tid] = M1[tid];   // A^128

    // T = A^160 = A^128 * A^32
    MATMUL(M0, sP[7], sP[5]);
    if (tid < 36) g_T[tid] = M0[tid];
    __syncthreads();

    // T powers
    MATMUL(M1, M0, M0);       if (tid < 36) sQ[0][tid] = M1[tid];  // T^2
    MATMUL(M2, M1, M1);       if (tid < 36) sQ[1][tid] = M2[tid];  // T^4
    MATMUL(M1, M2, M2);       if (tid < 36) sQ[2][tid] = M1[tid];  // T^8
    MATMUL(M2, M1, M1);       if (tid < 36) sQ[3][tid] = M2[tid];  // T^16
    MATMUL(M1, M2, M2);       if (tid < 36) sQ[4][tid] = M1[tid];  // T^32
    MATMUL(M2, M1, M1);       if (tid < 36) sQ[5][tid] = M2[tid];  // T^64
    if (tid < 36) g_T4[tid] = sQ[1][tid];
    __syncthreads();

    // T24 = T^16 * T^8
    MATMUL(M0, sQ[3], sQ[2]);
    if (tid < 36) g_T24[tid] = M0[tid];
    __syncthreads();

    // Tb = T^120 = T^64 * T^32 * T^16 * T^8
    MATMUL(M0, sQ[5], sQ[4]);   // T^96
    MATMUL(M1, M0, sQ[3]);      // T^112
    MATMUL(M2, M1, sQ[2]);      // T^120
    if (tid < 36) sTb[tid] = M2[tid];
    __syncthreads();

    // Tbp[p] = Tb^p
    if (tid < 36) {
        float idv = (tid % 7 == 0) ? 1.f : 0.f;
        M1[tid] = idv;
        g_Tbp[tid] = idv;
    }
    __syncthreads();
    for (int p = 1; p < NLOOK; p++) {
        MATMUL(M2, M1, sTb);
        if (tid < 36) { g_Tbp[p * 36 + tid] = M2[tid]; M1[tid] = M2[tid]; }
        __syncthreads();
    }

    // W[n] = A^(CHUNK-1-n) b (state weights); V[n] = c^T A^n (output weights)
    if (tid < CHUNK) {
        // W
        {
            int e = CHUNK - 1 - tid;
            float v[6];
#pragma unroll
            for (int j = 0; j < 6; j++) v[j] = (float)db[j];
#pragma unroll
            for (int k = 0; k < 8; k++) {
                if ((e >> k) & 1) {
                    float nv[6];
#pragma unroll
                    for (int j = 0; j < 6; j++) {
                        float acc = 0.f;
#pragma unroll
                        for (int kk = 0; kk < 6; kk++)
                            acc = fmaf(sP[k][j * 6 + kk], v[kk], acc);
                        nv[j] = acc;
                    }
#pragma unroll
                    for (int j = 0; j < 6; j++) v[j] = nv[j];
                }
            }
#pragma unroll
            for (int j = 0; j < 6; j++) g_W6[j][tid] = v[j];
        }
        // V (row vector times binary powers)
        {
            float v[6];
            float k5 = (float)scoef[5], k10 = (float)scoef[10];
            v[0] = k5 * k10; v[1] = 0.f; v[2] = k10; v[3] = 0.f; v[4] = 1.f; v[5] = 0.f;
            int e = tid;
#pragma unroll
            for (int k = 0; k < 8; k++) {
                if ((e >> k) & 1) {
                    float nv[6];
#pragma unroll
                    for (int j = 0; j < 6; j++) {
                        float acc = 0.f;
#pragma unroll
                        for (int kk = 0; kk < 6; kk++)
                            acc = fmaf(v[kk], sP[k][kk * 6 + j], acc);
                        nv[j] = acc;
                    }
#pragma unroll
                    for (int j = 0; j < 6; j++) v[j] = nv[j];
                }
            }
#pragma unroll
            for (int j = 0; j < 6; j++) g_V6[j][tid] = v[j];
        }
    }
}

// ---------------------------------------------------------------- fused ----

__device__ __forceinline__ float step_all(float u, float z[6], const float k[15]) {
    float y0 = fmaf(k[0], u, z[0]);
    float t0 = fmaf(k[3], z[0], z[1]);
    z[1] = fmaf(k[2], u, k[4] * z[0]);
    z[0] = fmaf(k[1], u, t0);
    float y1 = fmaf(k[5], y0, z[2]);
    float t1 = fmaf(k[8], z[2], z[3]);
    z[3] = fmaf(k[7], y0, k[9] * z[2]);
    z[2] = fmaf(k[6], y0, t1);
    float y2 = fmaf(k[10], y1, z[4]);
    float t2 = fmaf(k[13], z[4], z[5]);
    z[5] = fmaf(k[12], y1, k[14] * z[4]);
    z[4] = fmaf(k[11], y1, t2);
    return y2;
}

__device__ __forceinline__ void affine_sm(float s[6], const float* fv,
                                          const float* T) {
    float ns[6];
#pragma unroll
    for (int j = 0; j < 6; j++) {
        float acc = fv[j];
#pragma unroll
        for (int kk = 0; kk < 6; kk++) acc = fmaf(T[j * 6 + kk], s[kk], acc);
        ns[j] = acc;
    }
#pragma unroll
    for (int j = 0; j < 6; j++) s[j] = ns[j];
}

__global__ __launch_bounds__(THREADS) void fused_kernel(const float* __restrict__ x,
                                                        float* __restrict__ y) {
    __shared__ float sbuf[NWPB][WCH][36];     // per-warp transpose tiles
    __shared__ float sw6[6][CHUNK];
    __shared__ float sv6[6][CHUNK];
    __shared__ float sk[15];
    __shared__ float sT[36], sT4[36], sT24[36];
    __shared__ float sfin[BCH][6];
    __shared__ float ssga[NWPB][6][6];
    __shared__ float sWA[NWPB][6], sWE[NWPB][6];
    __shared__ float sSE[NWPB][6][6];
    __shared__ float sS[6];

    int tid = threadIdx.x, ws = tid >> 5, lane = tid & 31;
    int bid = blockIdx.x;
    int r = bid / BROW, jb = bid % BROW;
    const float4* xw4 = (const float4*)(x + (size_t)r * TLEN + (size_t)jb * BCH * CHUNK)
                        + (size_t)ws * WCH * C4;
    float4* yw4 = (float4*)(y + (size_t)r * TLEN + (size_t)jb * BCH * CHUNK)
                  + (size_t)ws * WCH * C4;

    for (int i = tid; i < 6 * CHUNK / 4; i += THREADS) {
        ((float4*)sw6)[i] = ((const float4*)g_W6)[i];
        ((float4*)sv6)[i] = ((const float4*)g_V6)[i];
    }
    if (tid < 36) { sT[tid] = g_T[tid]; sT4[tid] = g_T4[tid]; sT24[tid] = g_T24[tid]; }
    if (tid < 15) sk[tid] = g_coef[tid];
    __syncthreads();

    float (*buf)[36] = sbuf[ws];
    int ci = lane >> 3;                  // base chunk group within staging
    int si = lane & 7;                   // float4 slot

    // -------- sweep 1: serial filter from zero; write y0; keep finals ------
    {
        float kc[15];
#pragma unroll
        for (int i = 0; i < 15; i++) kc[i] = sk[i];
        float z[6] = {0, 0, 0, 0, 0, 0};
        float4 pre[6];
#pragma unroll
        for (int kq = 0; kq < 6; kq++)
            pre[kq] = xw4[(ci + kq * 4) * C4 + si];
#pragma unroll
        for (int t = 0; t < CHUNK / 32; t++) {
#pragma unroll
            for (int kq = 0; kq < 6; kq++)
                *(float4*)&buf[ci + kq * 4][si * 4] = pre[kq];
            __syncwarp();
            if (t < CHUNK / 32 - 1) {
#pragma unroll
                for (int kq = 0; kq < 6; kq++)
                    pre[kq] = xw4[(ci + kq * 4) * C4 + (t + 1) * 8 + si];
            }
            if (lane < WCH) {
                float4* my = (float4*)buf[lane];
#pragma unroll
                for (int q = 0; q < 8; q++) {
                    float4 v = my[q];
                    float4 ov;
                    ov.x = step_all(v.x, z, kc);
                    ov.y = step_all(v.y, z, kc);
                    ov.z = step_all(v.z, z, kc);
                    ov.w = step_all(v.w, z, kc);
                    my[q] = ov;
                }
            }
            __syncwarp();
#pragma unroll
            for (int kq = 0; kq < 6; kq++)
                yw4[(ci + kq * 4) * C4 + t * 8 + si] = *(const float4*)&buf[ci + kq * 4][si * 4];
            __syncwarp();
        }
        if (lane < WCH) {
            float* f = sfin[ws * WCH + lane];
#pragma unroll
            for (int j = 0; j < 6; j++) f[j] = z[j];
        }
    }
    __syncwarp();

    // -------- in-block scan tree + lookback --------------------------------
    if (lane < 6) {   // 6 subgroups of 4 chunks per warp
        float s[6] = {0, 0, 0, 0, 0, 0};
        for (int i = 0; i < 4; i++)
            affine_sm(s, sfin[ws * WCH + lane * 4 + i], sT);
#pragma unroll
        for (int z = 0; z < 6; z++) ssga[ws][lane][z] = s[z];
    }
    __syncwarp();
    if (lane == 0) {
        float s[6] = {0, 0, 0, 0, 0, 0};
        for (int k = 0; k < 6; k++) affine_sm(s, ssga[ws][k], sT4);
#pragma unroll
        for (int z = 0; z < 6; z++) sWA[ws][z] = s[z];
    }
    __syncthreads();

    if (tid == 0) {   // block aggregate; publish (forward progress first)
        float s[6] = {0, 0, 0, 0, 0, 0};
        for (int w = 0; w < NWPB; w++) affine_sm(s, sWA[w], sT24);
#pragma unroll
        for (int z = 0; z < 6; z++) __stcg(&g_F[bid * 6 + z], s[z]);
        __threadfence();
        atomicExch(&g_flag[bid], 1);
    }
    if (ws == 0) {    // lookback: lane p handles predecessor at distance p
        float acc[6] = {0, 0, 0, 0, 0, 0};
        if (lane < jb) {
            int q = bid - 1 - lane;
            volatile int* vf = &g_flag[q];
            while (*vf == 0) __nanosleep(32);
            __threadfence();
            float Fv[6];
#pragma unroll
            for (int z = 0; z < 6; z++) Fv[z] = __ldcg(&g_F[q * 6 + z]);
            const float* P = &g_Tbp[lane * 36];
#pragma unroll
            for (int z = 0; z < 6; z++) {
                float a = 0.f;
#pragma unroll
                for (int kk = 0; kk < 6; kk++) a = fmaf(P[z * 6 + kk], Fv[kk], a);
                acc[z] = a;
            }
        }
#pragma unroll
        for (int o = 16; o > 0; o >>= 1)
#pragma unroll
            for (int z = 0; z < 6; z++)
                acc[z] += __shfl_down_sync(0xFFFFFFFFu, acc[z], o);
        if (lane == 0) {
#pragma unroll
            for (int z = 0; z < 6; z++) sS[z] = acc[z];
        }
    }
    __syncthreads();

    if (tid == 0) {   // warp entry states
        float s[6];
#pragma unroll
        for (int z = 0; z < 6; z++) s[z] = sS[z];
        for (int w = 0; w < NWPB; w++) {
#pragma unroll
            for (int z = 0; z < 6; z++) sWE[w][z] = s[z];
            affine_sm(s, sWA[w], sT24);
        }
    }
    __syncthreads();
    if (lane == 0) {  // subgroup entry states within warp
        float s[6];
#pragma unroll
        for (int z = 0; z < 6; z++) s[z] = sWE[ws][z];
        for (int k = 0; k < 6; k++) {
#pragma unroll
            for (int z = 0; z < 6; z++) sSE[ws][k][z] = s[z];
            affine_sm(s, ssga[ws][k], sT4);
        }
    }
    __syncwarp();

    float zst[6] = {0, 0, 0, 0, 0, 0};
    if (lane < WCH) {           // per-chunk entry state
        int kg = lane >> 2, o = lane & 3;
#pragma unroll
        for (int z = 0; z < 6; z++) zst[z] = sSE[ws][kg][z];
        for (int i = 0; i < o; i++)
            affine_sm(zst, sfin[ws * WCH + kg * 4 + i], sT);
    }

    // -------- sweep 2: output correction y += V[n] . s_entry ---------------
    {
        float4 pre[6];
#pragma unroll
        for (int kq = 0; kq < 6; kq++)
            pre[kq] = yw4[(ci + kq * 4) * C4 + si];
#pragma unroll
        for (int t = 0; t < CHUNK / 32; t++) {
#pragma unroll
            for (int kq = 0; kq < 6; kq++)
                *(float4*)&buf[ci + kq * 4][si * 4] = pre[kq];
            __syncwarp();
            if (t < CHUNK / 32 - 1) {
#pragma unroll
                for (int kq = 0; kq < 6; kq++)
                    pre[kq] = yw4[(ci + kq * 4) * C4 + (t + 1) * 8 + si];
            }
            if (lane < WCH) {
                float4* my = (float4*)buf[lane];
#pragma unroll
                for (int q = 0; q < 8; q++) {
                    float4 v = my[q];
                    int n = t * 32 + q * 4;
                    float4 w0 = *(const float4*)&sv6[0][n];
                    float4 w1 = *(const float4*)&sv6[1][n];
                    float4 w2 = *(const float4*)&sv6[2][n];
                    float4 w3 = *(const float4*)&sv6[3][n];
                    float4 w4 = *(const float4*)&sv6[4][n];
                    float4 w5 = *(const float4*)&sv6[5][n];
                    v.x = fmaf(w5.x, zst[5], fmaf(w4.x, zst[4], fmaf(w3.x, zst[3],
                          fmaf(w2.x, zst[2], fmaf(w1.x, zst[1], fmaf(w0.x, zst[0], v.x))))));
                    v.y = fmaf(w5.y, zst[5], fmaf(w4.y, zst[4], fmaf(w3.y, zst[3],
                          fmaf(w2.y, zst[2], fmaf(w1.y, zst[1], fmaf(w0.y, zst[0], v.y))))));
                    v.z = fmaf(w5.z, zst[5], fmaf(w4.z, zst[4], fmaf(w3.z, zst[3],
                          fmaf(w2.z, zst[2], fmaf(w1.z, zst[1], fmaf(w0.z, zst[0], v.z))))));
                    v.w = fmaf(w5.w, zst[5], fmaf(w4.w, zst[4], fmaf(w3.w, zst[3],
                          fmaf(w2.w, zst[2], fmaf(w1.w, zst[1], fmaf(w0.w, zst[0], v.w))))));
                    my[q] = v;
                }
            }
            __syncwarp();
#pragma unroll
            for (int kq = 0; kq < 6; kq++)
                yw4[(ci + kq * 4) * C4 + t * 8 + si] = *(const float4*)&buf[ci + kq * 4][si * 4];
            __syncwarp();
        }
    }
}

// ----------------------------------------------------------------- launch --

extern "C" void kernel_launch(void* const* d_in, const int* in_sizes, int n_in,
                              void* d_out, int out_size) {
    const float* x   = (const float*)d_in[0];
    const float* lg  = (const float*)d_in[1];
    const float* mg  = (const float*)d_in[2];
    const float* mfc = (const float*)d_in[3];
    const float* mq  = (const float*)d_in[4];
    const float* hg  = (const float*)d_in[5];
    float* y = (float*)d_out;

    setup_kernel<<<1, 256>>>(lg, mg, mfc, mq, hg);
    fused_kernel<<<GRID, THREADS>>>(x, y);
}

// round 12
// speedup vs baseline: 1.6018x; 1.6018x over previous
#include <cuda_runtime.h>
#include <math.h>

// ToneStack: 3 cascaded low-shelf biquads over x:[64, 480000] fp32.
// Blocked-recurrence decomposition, 4 kernels:
//   pass_zero : warp-per-chunk dot-product reduction f = sum_n W[n] x[n]
//               (W in registers, one coalesced LDG.128 per chunk, butterfly)
//   scan_fused: per-row 3-level affine scan (smem-staged, float2 bulk copies)
//   pass_final: per-chunk serial filter from exact entry state (proven 37.6us)

#define TLEN   480000
#define NROW   64
#define CHUNK  128
#define CROW   3750            // chunks per row
#define NCH    (NROW * CROW)   // 240000
#define NWARP  (NCH / 32)      // 7500
#define PBLK   (NWARP / 4)     // 1875 blocks of 4 warps
#define NGSZ   30              // chunks per group
#define NGROUP 125             // groups per row
#define NSUPG  5
#define NSUP   25
#define GPAD   182             // group row stride (even -> float2 copies)
#define SCAN_SMEM (NGROUP * GPAD * 4)

__device__ float g_coef[15];          // per stage: b0, c1, c2, -a1, -a2
__device__ float g_T[36];             // A^CHUNK
__device__ float g_Tg[36];            // T^NGSZ
__device__ float g_Tsg[36];           // Tg^NSUPG
__device__ float g_W6[6][CHUNK];      // transposed reduction weights
__device__ float g_states[NCH * 6];   // finals, then overwritten with entries

// ---------------------------------------------------------------- setup ----

__device__ void shelf_coefs(double fc, double gdb, double Q, double* out) {
    const double PI = 3.14159265358979323846;
    double A  = pow(10.0, gdb / 40.0);
    double w0 = 2.0 * PI * fc / 48000.0;
    double al = sin(w0) / (2.0 * Q);
    double cw = cos(w0);
    double sq = sqrt(A);
    double b0 = A * ((A + 1.0) - (A - 1.0) * cw + 2.0 * sq * al);
    double b1 = 2.0 * A * ((A - 1.0) - (A + 1.0) * cw);
    double b2 = A * ((A + 1.0) - (A - 1.0) * cw - 2.0 * sq * al);
    double a0 = (A + 1.0) + (A - 1.0) * cw + 2.0 * sq * al;
    double a1 = -2.0 * ((A - 1.0) + (A + 1.0) * cw);
    double a2 = (A + 1.0) + (A - 1.0) * cw - 2.0 * sq * al;
    b0 /= a0; b1 /= a0; b2 /= a0; a1 /= a0; a2 /= a0;
    out[0] = b0;
    out[1] = b1 - a1 * b0;   // c1
    out[2] = b2 - a2 * b0;   // c2
    out[3] = -a1;
    out[4] = -a2;
}

#define MATMUL(D, A_, B_)                                                     \
    do {                                                                      \
        if (tid < 36) {                                                       \
            int r_ = tid / 6, c_ = tid % 6;                                   \
            float acc_ = 0.f;                                                 \
            for (int k_ = 0; k_ < 6; k_++)                                    \
                acc_ += (A_)[r_ * 6 + k_] * (B_)[k_ * 6 + c_];                \
            (D)[tid] = acc_;                                                  \
        }                                                                     \
        __syncthreads();                                                      \
    } while (0)

__global__ void setup_kernel(const float* lg, const float* mg, const float* mfc,
                             const float* mq, const float* hg) {
    __shared__ double scoef[15];
    __shared__ double db[6];
    __shared__ float sP[7][36];        // A^(2^k), k = 0..6
    __shared__ float M0[36], M1[36], M2[36], M3[36], M4[36];
    int tid = threadIdx.x;

    if (tid == 0) {
        double c[5];
        shelf_coefs(120.0, (double)*lg, (double)0.707f, c);
        for (int i = 0; i < 5; i++) { scoef[i] = c[i];      g_coef[i]      = (float)c[i]; }
        shelf_coefs((double)*mfc, (double)*mg, (double)*mq, c);
        for (int i = 0; i < 5; i++) { scoef[5 + i] = c[i];  g_coef[5 + i]  = (float)c[i]; }
        shelf_coefs(4000.0, (double)*hg, (double)0.707f, c);
        for (int i = 0; i < 5; i++) { scoef[10 + i] = c[i]; g_coef[10 + i] = (float)c[i]; }
    }
    __syncthreads();

    // One-step 6x6 homogeneous matrix A: column j = step(e_j, x=0)
    if (tid < 6) {
        double z[6] = {0, 0, 0, 0, 0, 0};
        z[tid] = 1.0;
        double u = 0.0;
        double ns[6];
        for (int st = 0; st < 3; st++) {
            double b0  = scoef[st * 5 + 0], c1 = scoef[st * 5 + 1], c2 = scoef[st * 5 + 2];
            double na1 = scoef[st * 5 + 3], na2 = scoef[st * 5 + 4];
            double z1 = z[2 * st], z2 = z[2 * st + 1];
            double y = b0 * u + z1;
            ns[2 * st]     = c1 * u + na1 * z1 + z2;
            ns[2 * st + 1] = c2 * u + na2 * z1;
            u = y;
        }
        for (int i = 0; i < 6; i++) M0[i * 6 + tid] = (float)ns[i];
    }
    if (tid == 0) {
        double y0 = scoef[0];
        double y1 = scoef[5] * y0;
        db[0] = scoef[1];  db[1] = scoef[2];
        db[2] = scoef[6] * y0;   db[3] = scoef[7] * y0;
        db[4] = scoef[11] * y1;  db[5] = scoef[12] * y1;
    }
    __syncthreads();

    // Squaring chain; stash A^(2^k).
    if (tid < 36) sP[0][tid] = M0[tid];
    __syncthreads();
    MATMUL(M1, M0, M0);   if (tid < 36) sP[1][tid] = M1[tid];   // A^2
    MATMUL(M0, M1, M1);   if (tid < 36) sP[2][tid] = M0[tid];   // A^4
    MATMUL(M1, M0, M0);   if (tid < 36) sP[3][tid] = M1[tid];   // A^8
    MATMUL(M0, M1, M1);   if (tid < 36) sP[4][tid] = M0[tid];   // A^16
    MATMUL(M1, M0, M0);   if (tid < 36) sP[5][tid] = M1[tid];   // A^32
    MATMUL(M0, M1, M1);   if (tid < 36) sP[6][tid] = M0[tid];   // A^64
    MATMUL(M1, M0, M0);                                          // A^128 = T
    if (tid < 36) { g_T[tid] = M1[tid]; M0[tid] = M1[tid]; }
    __syncthreads();

    // Tg = T^30 ; Tsg = Tg^5
    MATMUL(M1, M0, M0);   // T^2
    MATMUL(M2, M1, M1);   // T^4
    MATMUL(M3, M2, M2);   // T^8
    MATMUL(M4, M3, M3);   // T^16
    MATMUL(M0, M4, M3);   // T^24
    MATMUL(M3, M0, M2);   // T^28
    MATMUL(M2, M3, M1);   // T^30 = Tg
    if (tid < 36) g_Tg[tid] = M2[tid];
    __syncthreads();
    MATMUL(M1, M2, M2);   // Tg^2
    MATMUL(M0, M1, M1);   // Tg^4
    MATMUL(M4, M0, M2);   // Tg^5 = Tsg
    if (tid < 36) g_Tsg[tid] = M4[tid];
    __syncthreads();

    // W[n] = A^(127-n) b, one thread per n via binary power application
    if (tid < CHUNK) {
        int e = CHUNK - 1 - tid;
        float v[6];
#pragma unroll
        for (int j = 0; j < 6; j++) v[j] = (float)db[j];
#pragma unroll
        for (int k = 0; k < 7; k++) {
            if ((e >> k) & 1) {
                float nv[6];
#pragma unroll
                for (int j = 0; j < 6; j++) {
                    float acc = 0.f;
#pragma unroll
                    for (int kk = 0; kk < 6; kk++)
                        acc = fmaf(sP[k][j * 6 + kk], v[kk], acc);
                    nv[j] = acc;
                }
#pragma unroll
                for (int j = 0; j < 6; j++) v[j] = nv[j];
            }
        }
#pragma unroll
        for (int j = 0; j < 6; j++) g_W6[j][tid] = v[j];
    }
}

// ----------------------------------------------------- pass_zero (dot) ----

// One warp per chunk-span of 32 chunks. Lane L owns sample slots 4L..4L+3;
// its 6 weight-float4s are loop-invariant (24 registers). Per chunk: one
// coalesced LDG.128, 24 FMA, 6-value xor-butterfly, one coalesced store.
__global__ __launch_bounds__(128) void pass_zero(const float* __restrict__ x) {
    int w = blockIdx.x * 4 + (threadIdx.x >> 5);
    int lane = threadIdx.x & 31;

    float4 wr0 = ((const float4*)g_W6[0])[lane];
    float4 wr1 = ((const float4*)g_W6[1])[lane];
    float4 wr2 = ((const float4*)g_W6[2])[lane];
    float4 wr3 = ((const float4*)g_W6[3])[lane];
    float4 wr4 = ((const float4*)g_W6[4])[lane];
    float4 wr5 = ((const float4*)g_W6[5])[lane];

    const float4* xc = (const float4*)x + (size_t)w * 32 * (CHUNK / 4);
    float* sb = &g_states[(size_t)w * 32 * 6];

#pragma unroll 1
    for (int c = 0; c < 32; c += 4) {
        float4 xv[4];
#pragma unroll
        for (int u = 0; u < 4; u++)
            xv[u] = xc[(c + u) * (CHUNK / 4) + lane];
#pragma unroll
        for (int u = 0; u < 4; u++) {
            float4 v = xv[u];
            float f0 = fmaf(v.w, wr0.w, fmaf(v.z, wr0.z, fmaf(v.y, wr0.y, v.x * wr0.x)));
            float f1 = fmaf(v.w, wr1.w, fmaf(v.z, wr1.z, fmaf(v.y, wr1.y, v.x * wr1.x)));
            float f2 = fmaf(v.w, wr2.w, fmaf(v.z, wr2.z, fmaf(v.y, wr2.y, v.x * wr2.x)));
            float f3 = fmaf(v.w, wr3.w, fmaf(v.z, wr3.z, fmaf(v.y, wr3.y, v.x * wr3.x)));
            float f4 = fmaf(v.w, wr4.w, fmaf(v.z, wr4.z, fmaf(v.y, wr4.y, v.x * wr4.x)));
            float f5 = fmaf(v.w, wr5.w, fmaf(v.z, wr5.z, fmaf(v.y, wr5.y, v.x * wr5.x)));
#pragma unroll
            for (int o = 16; o > 0; o >>= 1) {
                f0 += __shfl_xor_sync(0xFFFFFFFFu, f0, o);
                f1 += __shfl_xor_sync(0xFFFFFFFFu, f1, o);
                f2 += __shfl_xor_sync(0xFFFFFFFFu, f2, o);
                f3 += __shfl_xor_sync(0xFFFFFFFFu, f3, o);
                f4 += __shfl_xor_sync(0xFFFFFFFFu, f4, o);
                f5 += __shfl_xor_sync(0xFFFFFFFFu, f5, o);
            }
            if (lane < 6) {
                float out = (lane == 0) ? f0 : (lane == 1) ? f1 : (lane == 2) ? f2
                          : (lane == 3) ? f3 : (lane == 4) ? f4 : f5;
                sb[(c + u) * 6 + lane] = out;
            }
        }
    }
}

// -------------------------------------------------------------- filtering --

__device__ __forceinline__ float step_all(float u, float z[6], const float k[15]) {
    float y0 = fmaf(k[0], u, z[0]);
    float t0 = fmaf(k[3], z[0], z[1]);
    z[1] = fmaf(k[2], u, k[4] * z[0]);
    z[0] = fmaf(k[1], u, t0);
    float y1 = fmaf(k[5], y0, z[2]);
    float t1 = fmaf(k[8], z[2], z[3]);
    z[3] = fmaf(k[7], y0, k[9] * z[2]);
    z[2] = fmaf(k[6], y0, t1);
    float y2 = fmaf(k[10], y1, z[4]);
    float t2 = fmaf(k[13], z[4], z[5]);
    z[5] = fmaf(k[12], y1, k[14] * z[4]);
    z[4] = fmaf(k[11], y1, t2);
    return y2;
}

__global__ __launch_bounds__(128) void pass_final(const float* __restrict__ x,
                                                  float* __restrict__ y) {
    __shared__ float sbuf[4][32][36];
    int wslot = threadIdx.x >> 5;
    int w = blockIdx.x * 4 + wslot;
    int lane = threadIdx.x & 31;
    float (*buf)[36] = sbuf[wslot];
    const float* xw = x + (size_t)w * (32 * CHUNK);
    float* yw = y + (size_t)w * (32 * CHUNK);

    float k[15];
#pragma unroll
    for (int i = 0; i < 15; i++) k[i] = g_coef[i];
    float z[6];
    const float* si = &g_states[(size_t)(w * 32 + lane) * 6];
#pragma unroll
    for (int j = 0; j < 6; j++) z[j] = si[j];

    int seg = lane >> 3;
    int off = (lane & 7) * 4;

    float4 pre[8];
#pragma unroll
    for (int q = 0; q < 8; q++)
        pre[q] = *(const float4*)(xw + (q * 4 + seg) * CHUNK + off);

#pragma unroll
    for (int t = 0; t < CHUNK / 32; t++) {
#pragma unroll
        for (int q = 0; q < 8; q++)
            *(float4*)&buf[q * 4 + seg][off] = pre[q];
        __syncwarp();
        if (t < CHUNK / 32 - 1) {
#pragma unroll
            for (int q = 0; q < 8; q++)
                pre[q] = *(const float4*)(xw + (q * 4 + seg) * CHUNK + (t + 1) * 32 + off);
        }
        float4* my = (float4*)buf[lane];
#pragma unroll
        for (int j = 0; j < 8; j++) {
            float4 v = my[j];
            float4 o;
            o.x = step_all(v.x, z, k);
            o.y = step_all(v.y, z, k);
            o.z = step_all(v.z, z, k);
            o.w = step_all(v.w, z, k);
            my[j] = o;
        }
        __syncwarp();
#pragma unroll
        for (int q = 0; q < 8; q++) {
            float4 v = *(const float4*)&buf[q * 4 + seg][off];
            *(float4*)(yw + (q * 4 + seg) * CHUNK + t * 32 + off) = v;
        }
        __syncwarp();
    }
}

// ------------------------------------------------------------ fused scan --

__device__ __forceinline__ void affine_step(float s[6], const float fv[6],
                                            const float T[36]) {
    float ns[6];
#pragma unroll
    for (int j = 0; j < 6; j++) {
        float acc = fv[j];
#pragma unroll
        for (int kk = 0; kk < 6; kk++) acc = fmaf(T[j * 6 + kk], s[kk], acc);
        ns[j] = acc;
    }
#pragma unroll
    for (int j = 0; j < 6; j++) s[j] = ns[j];
}

// One block per row; row's 22500 floats staged in padded dynamic smem via
// float2 bulk copies (256 threads); 3-level scan (125 groups of 30, 25
// supergroups of 5); entries written back over g_states.
__global__ __launch_bounds__(256) void scan_fused() {
    extern __shared__ float sf[];             // NGROUP * GPAD floats
    __shared__ float sT[36], sTg[36], sTsg[36];
    __shared__ float grp[NGROUP][6];
    __shared__ float sup[NSUP][6];
    int r = blockIdx.x, tid = threadIdx.x;
    float* gs = &g_states[(size_t)r * CROW * 6];

    // bulk load (float2, padded remap: elem 2*i2 -> group g, offset w)
    for (int i2 = tid; i2 < CROW * 6 / 2; i2 += 256) {
        int e = 2 * i2;
        int g = e / (NGSZ * 6);
        int woff = e - g * (NGSZ * 6);
        ((float2*)sf)[g * (GPAD / 2) + woff / 2] = ((const float2*)gs)[i2];
    }
    if (tid < 36) { sT[tid] = g_T[tid]; sTg[tid] = g_Tg[tid]; sTsg[tid] = g_Tsg[tid]; }
    __syncthreads();

    // phase 1: zero-entry scan within each group -> group final
    if (tid < NGROUP) {
        float T[36];
#pragma unroll
        for (int i = 0; i < 36; i++) T[i] = sT[i];
        const float* f = &sf[tid * GPAD];
        float s[6] = {0, 0, 0, 0, 0, 0};
        for (int i = 0; i < NGSZ; i++) {
            float fv[6];
#pragma unroll
            for (int j = 0; j < 6; j++) fv[j] = f[i * 6 + j];
            affine_step(s, fv, T);
        }
#pragma unroll
        for (int j = 0; j < 6; j++) grp[tid][j] = s[j];
    }
    __syncthreads();

    // phase 2a: zero-entry scan of 5 group finals -> supergroup final
    if (tid < NSUP) {
        float T[36];
#pragma unroll
        for (int i = 0; i < 36; i++) T[i] = sTg[i];
        float s[6] = {0, 0, 0, 0, 0, 0};
        for (int i = 0; i < NSUPG; i++) affine_step(s, grp[tid * NSUPG + i], T);
#pragma unroll
        for (int j = 0; j < 6; j++) sup[tid][j] = s[j];
    }
    __syncthreads();

    // phase 2b: serial scan over supergroups; sup[] becomes entry states
    if (tid == 0) {
        float T[36];
#pragma unroll
        for (int i = 0; i < 36; i++) T[i] = sTsg[i];
        float s[6] = {0, 0, 0, 0, 0, 0};
        for (int g = 0; g < NSUP; g++) {
            float fv[6];
#pragma unroll
            for (int j = 0; j < 6; j++) { fv[j] = sup[g][j]; sup[g][j] = s[j]; }
            affine_step(s, fv, T);
        }
    }
    __syncthreads();

    // phase 2c: group entry states from supergroup entry
    if (tid < NSUP) {
        float T[36];
#pragma unroll
        for (int i = 0; i < 36; i++) T[i] = sTg[i];
        float s[6];
#pragma unroll
        for (int j = 0; j < 6; j++) s[j] = sup[tid][j];
        for (int i = 0; i < NSUPG; i++) {
            float fv[6];
            int gi = tid * NSUPG + i;
#pragma unroll
            for (int j = 0; j < 6; j++) { fv[j] = grp[gi][j]; grp[gi][j] = s[j]; }
            affine_step(s, fv, T);
        }
    }
    __syncthreads();

    // phase 3: per-chunk entry states, overwrite staged finals
    if (tid < NGROUP) {
        float T[36];
#pragma unroll
        for (int i = 0; i < 36; i++) T[i] = sT[i];
        float* f = &sf[tid * GPAD];
        float s[6];
#pragma unroll
        for (int j = 0; j < 6; j++) s[j] = grp[tid][j];
        for (int i = 0; i < NGSZ; i++) {
            float fv[6];
#pragma unroll
            for (int j = 0; j < 6; j++) { fv[j] = f[i * 6 + j]; f[i * 6 + j] = s[j]; }
            affine_step(s, fv, T);
        }
    }
    __syncthreads();

    // bulk store
    for (int i2 = tid; i2 < CROW * 6 / 2; i2 += 256) {
        int e = 2 * i2;
        int g = e / (NGSZ * 6);
        int woff = e - g * (NGSZ * 6);
        ((float2*)gs)[i2] = ((const float2*)sf)[g * (GPAD / 2) + woff / 2];
    }
}

// ----------------------------------------------------------------- launch --

extern "C" void kernel_launch(void* const* d_in, const int* in_sizes, int n_in,
                              void* d_out, int out_size) {
    const float* x   = (const float*)d_in[0];
    const float* lg  = (const float*)d_in[1];
    const float* mg  = (const float*)d_in[2];
    const float* mfc = (const float*)d_in[3];
    const float* mq  = (const float*)d_in[4];
    const float* hg  = (const float*)d_in[5];
    float* y = (float*)d_out;

    cudaFuncSetAttribute(scan_fused, cudaFuncAttributeMaxDynamicSharedMemorySize,
                         SCAN_SMEM);

    setup_kernel<<<1, 256>>>(lg, mg, mfc, mq, hg);
    pass_zero<<<PBLK, 128>>>(x);
    scan_fused<<<NROW, 256, SCAN_SMEM>>>();
    pass_final<<<PBLK, 128>>>(x, y);
}

// round 13
// speedup vs baseline: 2.2769x; 1.4215x over previous
#include <cuda_runtime.h>
#include <math.h>

// ToneStack: 3 cascaded low-shelf biquads over x:[64, 480000] fp32.
// Blocked-recurrence decomposition, 4 kernels:
//   setup     : fp32 coefficient + matrix-power tables (MUFU, parallel W)
//   pass_zero : per-chunk serial filter from zero state -> finals
//               (pass_final shape minus the y stores; FMA-bound)
//   scan_fused: per-row 3-level affine scan (smem-staged, float2 bulk copies)
//   pass_final: per-chunk serial filter from exact entry state (proven 37us)

#define TLEN   480000
#define NROW   64
#define CHUNK  128
#define CROW   3750            // chunks per row
#define NCH    (NROW * CROW)   // 240000
#define NWARP  (NCH / 32)      // 7500
#define PBLK   (NWARP / 4)     // 1875 blocks of 4 warps
#define NGSZ   30              // chunks per group
#define NGROUP 125             // groups per row
#define NSUPG  5
#define NSUP   25
#define GPAD   182             // group row stride (even -> float2 copies)
#define SCAN_SMEM (NGROUP * GPAD * 4)

__device__ float g_coef[15];          // per stage: b0, c1, c2, -a1, -a2
__device__ float g_T[36];             // A^CHUNK
__device__ float g_Tg[36];            // T^NGSZ
__device__ float g_Tsg[36];           // Tg^NSUPG
__device__ float g_states[NCH * 6];   // finals, then overwritten with entries

// ---------------------------------------------------------------- setup ----

__device__ void shelf_coefs_f(float fc, float gdb, float Q, float* out) {
    const float PI = 3.14159265358979323846f;
    float A  = exp10f(gdb * (1.0f / 40.0f));
    float w0 = 2.0f * PI * fc / 48000.0f;
    float al = sinf(w0) / (2.0f * Q);
    float cw = cosf(w0);
    float sq = sqrtf(A);
    float b0 = A * ((A + 1.0f) - (A - 1.0f) * cw + 2.0f * sq * al);
    float b1 = 2.0f * A * ((A - 1.0f) - (A + 1.0f) * cw);
    float b2 = A * ((A + 1.0f) - (A - 1.0f) * cw - 2.0f * sq * al);
    float a0 = (A + 1.0f) + (A - 1.0f) * cw + 2.0f * sq * al;
    float a1 = -2.0f * ((A - 1.0f) + (A + 1.0f) * cw);
    float a2 = (A + 1.0f) + (A - 1.0f) * cw - 2.0f * sq * al;
    float inv = 1.0f / a0;
    b0 *= inv; b1 *= inv; b2 *= inv; a1 *= inv; a2 *= inv;
    out[0] = b0;
    out[1] = b1 - a1 * b0;   // c1
    out[2] = b2 - a2 * b0;   // c2
    out[3] = -a1;
    out[4] = -a2;
}

#define MATMUL(D, A_, B_)                                                     \
    do {                                                                      \
        if (tid < 36) {                                                       \
            int r_ = tid / 6, c_ = tid % 6;                                   \
            float acc_ = 0.f;                                                 \
            for (int k_ = 0; k_ < 6; k_++)                                    \
                acc_ += (A_)[r_ * 6 + k_] * (B_)[k_ * 6 + c_];                \
            (D)[tid] = acc_;                                                  \
        }                                                                     \
        __syncthreads();                                                      \
    } while (0)

__global__ void setup_kernel(const float* lg, const float* mg, const float* mfc,
                             const float* mq, const float* hg) {
    __shared__ float scoef[15];
    __shared__ float M0[36], M1[36], M2[36], M3[36], M4[36];
    int tid = threadIdx.x;

    // fp32 coefficient derivation (matches reference's own float32 math);
    // three independent threads, MUFU-speed.
    if (tid == 0) {
        float c[5];
        shelf_coefs_f(120.0f, *lg, 0.707f, c);
        for (int i = 0; i < 5; i++) { scoef[i] = c[i]; g_coef[i] = c[i]; }
    } else if (tid == 1) {
        float c[5];
        shelf_coefs_f(*mfc, *mg, *mq, c);
        for (int i = 0; i < 5; i++) { scoef[5 + i] = c[i]; g_coef[5 + i] = c[i]; }
    } else if (tid == 2) {
        float c[5];
        shelf_coefs_f(4000.0f, *hg, 0.707f, c);
        for (int i = 0; i < 5; i++) { scoef[10 + i] = c[i]; g_coef[10 + i] = c[i]; }
    }
    __syncthreads();

    // One-step 6x6 homogeneous matrix A: column j = step(e_j, x=0)
    if (tid < 6) {
        float z[6] = {0, 0, 0, 0, 0, 0};
        z[tid] = 1.0f;
        float u = 0.0f;
        float ns[6];
        for (int st = 0; st < 3; st++) {
            float b0  = scoef[st * 5 + 0], c1 = scoef[st * 5 + 1], c2 = scoef[st * 5 + 2];
            float na1 = scoef[st * 5 + 3], na2 = scoef[st * 5 + 4];
            float z1 = z[2 * st], z2 = z[2 * st + 1];
            float y = b0 * u + z1;
            ns[2 * st]     = c1 * u + na1 * z1 + z2;
            ns[2 * st + 1] = c2 * u + na2 * z1;
            u = y;
        }
        for (int i = 0; i < 6; i++) M0[i * 6 + tid] = ns[i];
    }
    __syncthreads();

    // T = A^128 : 7 squarings (ends in M1)
    MATMUL(M1, M0, M0);   // A^2
    MATMUL(M0, M1, M1);   // A^4
    MATMUL(M1, M0, M0);   // A^8
    MATMUL(M0, M1, M1);   // A^16
    MATMUL(M1, M0, M0);   // A^32
    MATMUL(M0, M1, M1);   // A^64
    MATMUL(M1, M0, M0);   // A^128 = T
    if (tid < 36) { g_T[tid] = M1[tid]; M0[tid] = M1[tid]; }
    __syncthreads();

    // Tg = T^30 ; Tsg = Tg^5
    MATMUL(M1, M0, M0);   // T^2
    MATMUL(M2, M1, M1);   // T^4
    MATMUL(M3, M2, M2);   // T^8
    MATMUL(M4, M3, M3);   // T^16
    MATMUL(M0, M4, M3);   // T^24
    MATMUL(M3, M0, M2);   // T^28
    MATMUL(M2, M3, M1);   // T^30 = Tg
    if (tid < 36) g_Tg[tid] = M2[tid];
    __syncthreads();
    MATMUL(M1, M2, M2);   // Tg^2
    MATMUL(M0, M1, M1);   // Tg^4
    MATMUL(M4, M0, M2);   // Tg^5 = Tsg
    if (tid < 36) g_Tsg[tid] = M4[tid];
}

// -------------------------------------------------------------- filtering --

__device__ __forceinline__ float step_all(float u, float z[6], const float k[15]) {
    float y0 = fmaf(k[0], u, z[0]);
    float t0 = fmaf(k[3], z[0], z[1]);
    z[1] = fmaf(k[2], u, k[4] * z[0]);
    z[0] = fmaf(k[1], u, t0);
    float y1 = fmaf(k[5], y0, z[2]);
    float t1 = fmaf(k[8], z[2], z[3]);
    z[3] = fmaf(k[7], y0, k[9] * z[2]);
    z[2] = fmaf(k[6], y0, t1);
    float y2 = fmaf(k[10], y1, z[4]);
    float t2 = fmaf(k[13], z[4], z[5]);
    z[5] = fmaf(k[12], y1, k[14] * z[4]);
    z[4] = fmaf(k[11], y1, t2);
    return y2;
}

// Tile: 32 chunks x 32 samples, rows padded to 36 floats. seg = lane>>3,
// off = (lane&7)*4: every LDG/STG.128 covers 4 full 128B lines.

// pass_zero: serial filter from zero state; record only the final state.
__global__ __launch_bounds__(128) void pass_zero(const float* __restrict__ x) {
    __shared__ float sbuf[4][32][36];
    int wslot = threadIdx.x >> 5;
    int w = blockIdx.x * 4 + wslot;
    int lane = threadIdx.x & 31;
    float (*buf)[36] = sbuf[wslot];
    const float* xw = x + (size_t)w * (32 * CHUNK);

    float k[15];
#pragma unroll
    for (int i = 0; i < 15; i++) k[i] = g_coef[i];
    float z[6] = {0, 0, 0, 0, 0, 0};

    int seg = lane >> 3;
    int off = (lane & 7) * 4;

    float4 pre[8];
#pragma unroll
    for (int q = 0; q < 8; q++)
        pre[q] = *(const float4*)(xw + (q * 4 + seg) * CHUNK + off);

#pragma unroll
    for (int t = 0; t < CHUNK / 32; t++) {
#pragma unroll
        for (int q = 0; q < 8; q++)
            *(float4*)&buf[q * 4 + seg][off] = pre[q];
        __syncwarp();
        if (t < CHUNK / 32 - 1) {
#pragma unroll
            for (int q = 0; q < 8; q++)
                pre[q] = *(const float4*)(xw + (q * 4 + seg) * CHUNK + (t + 1) * 32 + off);
        }
        const float4* my = (const float4*)buf[lane];
#pragma unroll
        for (int j = 0; j < 8; j++) {
            float4 v = my[j];
            step_all(v.x, z, k);
            step_all(v.y, z, k);
            step_all(v.z, z, k);
            step_all(v.w, z, k);
        }
        __syncwarp();
    }
    float* f = &g_states[(size_t)(w * 32 + lane) * 6];
#pragma unroll
    for (int j = 0; j < 6; j++) f[j] = z[j];
}

__global__ __launch_bounds__(128) void pass_final(const float* __restrict__ x,
                                                  float* __restrict__ y) {
    __shared__ float sbuf[4][32][36];
    int wslot = threadIdx.x >> 5;
    int w = blockIdx.x * 4 + wslot;
    int lane = threadIdx.x & 31;
    float (*buf)[36] = sbuf[wslot];
    const float* xw = x + (size_t)w * (32 * CHUNK);
    float* yw = y + (size_t)w * (32 * CHUNK);

    float k[15];
#pragma unroll
    for (int i = 0; i < 15; i++) k[i] = g_coef[i];
    float z[6];
    const float* si = &g_states[(size_t)(w * 32 + lane) * 6];
#pragma unroll
    for (int j = 0; j < 6; j++) z[j] = si[j];

    int seg = lane >> 3;
    int off = (lane & 7) * 4;

    float4 pre[8];
#pragma unroll
    for (int q = 0; q < 8; q++)
        pre[q] = *(const float4*)(xw + (q * 4 + seg) * CHUNK + off);

#pragma unroll
    for (int t = 0; t < CHUNK / 32; t++) {
#pragma unroll
        for (int q = 0; q < 8; q++)
            *(float4*)&buf[q * 4 + seg][off] = pre[q];
        __syncwarp();
        if (t < CHUNK / 32 - 1) {
#pragma unroll
            for (int q = 0; q < 8; q++)
                pre[q] = *(const float4*)(xw + (q * 4 + seg) * CHUNK + (t + 1) * 32 + off);
        }
        float4* my = (float4*)buf[lane];
#pragma unroll
        for (int j = 0; j < 8; j++) {
            float4 v = my[j];
            float4 o;
            o.x = step_all(v.x, z, k);
            o.y = step_all(v.y, z, k);
            o.z = step_all(v.z, z, k);
            o.w = step_all(v.w, z, k);
            my[j] = o;
        }
        __syncwarp();
#pragma unroll
        for (int q = 0; q < 8; q++) {
            float4 v = *(const float4*)&buf[q * 4 + seg][off];
            *(float4*)(yw + (q * 4 + seg) * CHUNK + t * 32 + off) = v;
        }
        __syncwarp();
    }
}

// ------------------------------------------------------------ fused scan --

__device__ __forceinline__ void affine_step(float s[6], const float fv[6],
                                            const float T[36]) {
    float ns[6];
#pragma unroll
    for (int j = 0; j < 6; j++) {
        float acc = fv[j];
#pragma unroll
        for (int kk = 0; kk < 6; kk++) acc = fmaf(T[j * 6 + kk], s[kk], acc);
        ns[j] = acc;
    }
#pragma unroll
    for (int j = 0; j < 6; j++) s[j] = ns[j];
}

// One block per row; row's 22500 floats staged in padded dynamic smem via
// float2 bulk copies (256 threads); 3-level scan; entries written back.
__global__ __launch_bounds__(256) void scan_fused() {
    extern __shared__ float sf[];             // NGROUP * GPAD floats
    __shared__ float sT[36], sTg[36], sTsg[36];
    __shared__ float grp[NGROUP][6];
    __shared__ float sup[NSUP][6];
    int r = blockIdx.x, tid = threadIdx.x;
    float* gs = &g_states[(size_t)r * CROW * 6];

    for (int i2 = tid; i2 < CROW * 6 / 2; i2 += 256) {
        int e = 2 * i2;
        int g = e / (NGSZ * 6);
        int woff = e - g * (NGSZ * 6);
        ((float2*)sf)[g * (GPAD / 2) + woff / 2] = ((const float2*)gs)[i2];
    }
    if (tid < 36) { sT[tid] = g_T[tid]; sTg[tid] = g_Tg[tid]; sTsg[tid] = g_Tsg[tid]; }
    __syncthreads();

    // phase 1: zero-entry scan within each group -> group final
    if (tid < NGROUP) {
        float T[36];
#pragma unroll
        for (int i = 0; i < 36; i++) T[i] = sT[i];
        const float* f = &sf[tid * GPAD];
        float s[6] = {0, 0, 0, 0, 0, 0};
        for (int i = 0; i < NGSZ; i++) {
            float fv[6];
#pragma unroll
            for (int j = 0; j < 6; j++) fv[j] = f[i * 6 + j];
            affine_step(s, fv, T);
        }
#pragma unroll
        for (int j = 0; j < 6; j++) grp[tid][j] = s[j];
    }
    __syncthreads();

    // phase 2a: zero-entry scan of 5 group finals -> supergroup final
    if (tid < NSUP) {
        float T[36];
#pragma unroll
        for (int i = 0; i < 36; i++) T[i] = sTg[i];
        float s[6] = {0, 0, 0, 0, 0, 0};
        for (int i = 0; i < NSUPG; i++) affine_step(s, grp[tid * NSUPG + i], T);
#pragma unroll
        for (int j = 0; j < 6; j++) sup[tid][j] = s[j];
    }
    __syncthreads();

    // phase 2b: serial scan over supergroups; sup[] becomes entry states
    if (tid == 0) {
        float T[36];
#pragma unroll
        for (int i = 0; i < 36; i++) T[i] = sTsg[i];
        float s[6] = {0, 0, 0, 0, 0, 0};
        for (int g = 0; g < NSUP; g++) {
            float fv[6];
#pragma unroll
            for (int j = 0; j < 6; j++) { fv[j] = sup[g][j]; sup[g][j] = s[j]; }
            affine_step(s, fv, T);
        }
    }
    __syncthreads();

    // phase 2c: group entry states from supergroup entry
    if (tid < NSUP) {
        float T[36];
#pragma unroll
        for (int i = 0; i < 36; i++) T[i] = sTg[i];
        float s[6];
#pragma unroll
        for (int j = 0; j < 6; j++) s[j] = sup[tid][j];
        for (int i = 0; i < NSUPG; i++) {
            float fv[6];
            int gi = tid * NSUPG + i;
#pragma unroll
            for (int j = 0; j < 6; j++) { fv[j] = grp[gi][j]; grp[gi][j] = s[j]; }
            affine_step(s, fv, T);
        }
    }
    __syncthreads();

    // phase 3: per-chunk entry states, overwrite staged finals
    if (tid < NGROUP) {
        float T[36];
#pragma unroll
        for (int i = 0; i < 36; i++) T[i] = sT[i];
        float* f = &sf[tid * GPAD];
        float s[6];
#pragma unroll
        for (int j = 0; j < 6; j++) s[j] = grp[tid][j];
        for (int i = 0; i < NGSZ; i++) {
            float fv[6];
#pragma unroll
            for (int j = 0; j < 6; j++) { fv[j] = f[i * 6 + j]; f[i * 6 + j] = s[j]; }
            affine_step(s, fv, T);
        }
    }
    __syncthreads();

    for (int i2 = tid; i2 < CROW * 6 / 2; i2 += 256) {
        int e = 2 * i2;
        int g = e / (NGSZ * 6);
        int woff = e - g * (NGSZ * 6);
        ((float2*)gs)[i2] = ((const float2*)sf)[g * (GPAD / 2) + woff / 2];
    }
}

// ----------------------------------------------------------------- launch --

extern "C" void kernel_launch(void* const* d_in, const int* in_sizes, int n_in,
                              void* d_out, int out_size) {
    const float* x   = (const float*)d_in[0];
    const float* lg  = (const float*)d_in[1];
    const float* mg  = (const float*)d_in[2];
    const float* mfc = (const float*)d_in[3];
    const float* mq  = (const float*)d_in[4];
    const float* hg  = (const float*)d_in[5];
    float* y = (float*)d_out;

    cudaFuncSetAttribute(scan_fused, cudaFuncAttributeMaxDynamicSharedMemorySize,
                         SCAN_SMEM);

    setup_kernel<<<1, 256>>>(lg, mg, mfc, mq, hg);
    pass_zero<<<PBLK, 128>>>(x);
    scan_fused<<<NROW, 256, SCAN_SMEM>>>();
    pass_final<<<PBLK, 128>>>(x, y);
}